// round 16
// baseline (speedup 1.0000x reference)
#include <cuda_runtime.h>
#include <cuda_fp16.h>
#include <math.h>
#include <stdint.h>

// ---------------- shapes ----------------
// B=2, S=4096, D=2048, H=16, DK=DV=128, SEG=512, NSEG=8, DH=8192, M=B*S=8192
// QKV fused (half): stride 6144 (Q at col 0, K at 2048, V at 4096)

// ---------------- scratch ----------------
static __device__ __half g_qkv[8192 * 6144];
static __device__ __half g_xh[8192 * 2048];
static __device__ __half g_att[8192 * 2048];
static __device__ float  g_P[2 * 16 * 8 * 128 * 128];
static __device__ float  g_Mpre[2 * 16 * 8 * 128 * 128];
static __device__ float  g_zz[2 * 16 * 8 * 128];
static __device__ float  g_zpre[2 * 16 * 8 * 128];
static __device__ __half g_ao[8192 * 2048];
static __device__ __half g_hb[8192 * 8192];
static __device__ float  g_yb[8192 * 2048];
static __device__ __half g_WqkvT[6144 * 2048];
static __device__ __half g_WoT[2048 * 2048];
static __device__ __half g_W1T[8192 * 2048];
static __device__ __half g_W2T[2048 * 8192];

// ---------------- helpers ----------------
__device__ __forceinline__ uint32_t smem_u32(const void* p) {
    uint32_t a;
    asm("{ .reg .u64 t; cvta.to.shared.u64 t, %1; cvt.u32.u64 %0, t; }" : "=r"(a) : "l"(p));
    return a;
}
__device__ __forceinline__ void cp16(uint32_t dst, const void* src) {
    asm volatile("cp.async.cg.shared.global [%0], [%1], 16;" :: "r"(dst), "l"(src) : "memory");
}
__device__ __forceinline__ void mma_f16(float* c, const uint32_t* a, const uint32_t* b) {
    asm volatile("mma.sync.aligned.m16n8k16.row.col.f32.f16.f16.f32 "
        "{%0,%1,%2,%3}, {%4,%5,%6,%7}, {%8,%9}, {%0,%1,%2,%3};"
        : "+f"(c[0]), "+f"(c[1]), "+f"(c[2]), "+f"(c[3])
        : "r"(a[0]), "r"(a[1]), "r"(a[2]), "r"(a[3]), "r"(b[0]), "r"(b[1]));
}
__device__ __forceinline__ void ldsm4(uint32_t& r0, uint32_t& r1, uint32_t& r2, uint32_t& r3,
                                      uint32_t addr) {
    asm volatile("ldmatrix.sync.aligned.m8n8.x4.shared.b16 {%0,%1,%2,%3}, [%4];"
        : "=r"(r0), "=r"(r1), "=r"(r2), "=r"(r3) : "r"(addr));
}
__device__ __forceinline__ void ldsm4t(uint32_t& r0, uint32_t& r1, uint32_t& r2, uint32_t& r3,
                                       uint32_t addr) {
    asm volatile("ldmatrix.sync.aligned.m8n8.x4.trans.shared.b16 {%0,%1,%2,%3}, [%4];"
        : "=r"(r0), "=r"(r1), "=r"(r2), "=r"(r3) : "r"(addr));
}
__device__ __forceinline__ uint32_t packh2(float a, float b) {
    __half2 h = __floats2half2_rn(a, b);
    return *(uint32_t*)&h;
}
__device__ __forceinline__ float elu1(float x) {
    return x > 0.f ? x + 1.f : __expf(x);
}

// ---------------- fp16 tensor-core GEMM (128x128, BK=64, 3-stage, single-barrier) ----------------
#define GROWS 72
#define GSTAGE_H (128 * GROWS * 2)
#define GEMM_SMEM (3 * GSTAGE_H * 2)

template <bool BIAS, bool RELU, typename OUTT>
__global__ __launch_bounds__(256, 2) void gemm_mma(
    const __half* __restrict__ A, const __half* __restrict__ Bt,
    const float* __restrict__ bias, OUTT* __restrict__ C,
    int Nn, int K)
{
    extern __shared__ __half smh[];
    const int tid = threadIdx.x;
    const int wid = tid >> 5, lane = tid & 31;
    const int group = lane >> 2, tig = lane & 3;
    const int wm = wid >> 2, wn = wid & 3;
    const int m0 = blockIdx.y * 128, n0 = blockIdx.x * 128;
    const int nt = K >> 6;

    const int lrow = tid >> 3;
    const int lc   = (tid & 7) << 3;

    const int a_off = (wm * 64 + (lane & 15)) * GROWS + ((lane >> 4) << 3);
    const int b_off = (wn * 32 + ((lane >> 4) << 3) + (lane & 7)) * GROWS + (((lane >> 3) & 1) << 3);

#pragma unroll
    for (int t = 0; t < 2; ++t) {
        __half* As = smh + t * GSTAGE_H;
        __half* Bs = As + 128 * GROWS;
        const int k0 = t * 64;
#pragma unroll
        for (int j = 0; j < 4; ++j) {
            int row = lrow + j * 32;
            cp16(smem_u32(As + row * GROWS + lc), A + (size_t)(m0 + row) * K + k0 + lc);
            cp16(smem_u32(Bs + row * GROWS + lc), Bt + (size_t)(n0 + row) * K + k0 + lc);
        }
        asm volatile("cp.async.commit_group;" ::: "memory");
    }

    float acc[4][4][4] = {};

    for (int t = 0; t < nt; ++t) {
        asm volatile("cp.async.wait_group 1;" ::: "memory");
        __syncthreads();

        const __half* As = smh + (t % 3) * GSTAGE_H;
        const __half* Bs = As + 128 * GROWS;

#pragma unroll
        for (int ks = 0; ks < 4; ++ks) {
            uint32_t af[4][4], bf[4][2];
#pragma unroll
            for (int mf = 0; mf < 4; ++mf)
                ldsm4(af[mf][0], af[mf][1], af[mf][2], af[mf][3],
                      smem_u32(As + a_off + mf * 16 * GROWS + ks * 16));
#pragma unroll
            for (int pr = 0; pr < 2; ++pr)
                ldsm4(bf[2 * pr][0], bf[2 * pr][1], bf[2 * pr + 1][0], bf[2 * pr + 1][1],
                      smem_u32(Bs + b_off + pr * 16 * GROWS + ks * 16));
#pragma unroll
            for (int mf = 0; mf < 4; ++mf)
#pragma unroll
                for (int nf = 0; nf < 4; ++nf)
                    mma_f16(acc[mf][nf], af[mf], bf[nf]);
        }

        if (t + 2 < nt) {
            const int s = (t + 2) % 3;
            __half* Asw = smh + s * GSTAGE_H;
            __half* Bsw = Asw + 128 * GROWS;
            const int k0 = (t + 2) * 64;
#pragma unroll
            for (int j = 0; j < 4; ++j) {
                int row = lrow + j * 32;
                cp16(smem_u32(Asw + row * GROWS + lc), A + (size_t)(m0 + row) * K + k0 + lc);
                cp16(smem_u32(Bsw + row * GROWS + lc), Bt + (size_t)(n0 + row) * K + k0 + lc);
            }
        }
        asm volatile("cp.async.commit_group;" ::: "memory");
    }

#pragma unroll
    for (int mf = 0; mf < 4; ++mf) {
        const int row = m0 + wm * 64 + mf * 16 + group;
#pragma unroll
        for (int nf = 0; nf < 4; ++nf) {
            const int col = n0 + wn * 32 + nf * 8 + 2 * tig;
            float2 v0 = make_float2(acc[mf][nf][0], acc[mf][nf][1]);
            float2 v1 = make_float2(acc[mf][nf][2], acc[mf][nf][3]);
            if (BIAS) {
                float b0 = bias[col], b1 = bias[col + 1];
                v0.x += b0; v0.y += b1; v1.x += b0; v1.y += b1;
            }
            if (RELU) {
                v0.x = fmaxf(v0.x, 0.f); v0.y = fmaxf(v0.y, 0.f);
                v1.x = fmaxf(v1.x, 0.f); v1.y = fmaxf(v1.y, 0.f);
            }
            if constexpr (sizeof(OUTT) == 4) {
                *(float2*)&C[(size_t)row * Nn + col] = v0;
                *(float2*)&C[(size_t)(row + 8) * Nn + col] = v1;
            } else {
                *(__half2*)&C[(size_t)row * Nn + col] = __floats2half2_rn(v0.x, v0.y);
                *(__half2*)&C[(size_t)(row + 8) * Nn + col] = __floats2half2_rn(v1.x, v1.y);
            }
        }
    }
}

// ---------------- fp32 -> fp16 convert ----------------
__global__ __launch_bounds__(256) void cvt_h(const float* __restrict__ S, __half* __restrict__ D)
{
    const size_t i = ((size_t)blockIdx.x * 256 + threadIdx.x) * 8;
    float4 a = *(const float4*)&S[i];
    float4 b = *(const float4*)&S[i + 4];
    __half2 h[4] = {
        __floats2half2_rn(a.x, a.y), __floats2half2_rn(a.z, a.w),
        __floats2half2_rn(b.x, b.y), __floats2half2_rn(b.z, b.w)
    };
    *(uint4*)&D[i] = *(uint4*)h;
}

// ---------------- weight transpose -> fp16 ----------------
__global__ __launch_bounds__(256) void transpose_h(
    const float* __restrict__ S, __half* __restrict__ D, int R, int C)
{
    __shared__ float t[32][33];
    const int bx = blockIdx.x * 32, by = blockIdx.y * 32;
    const int lx = threadIdx.x & 31, ly = threadIdx.x >> 5;
#pragma unroll
    for (int i = 0; i < 32; i += 8)
        t[ly + i][lx] = S[(size_t)(by + ly + i) * C + bx + lx];
    __syncthreads();
#pragma unroll
    for (int i = 0; i < 32; i += 8)
        D[(size_t)(bx + ly + i) * R + by + lx] = __float2half(t[lx][ly + i]);
}

// 4-way merged 2048x2048 transpose
__global__ __launch_bounds__(256) void transpose4_h(
    const float* __restrict__ S0, const float* __restrict__ S1,
    const float* __restrict__ S2, const float* __restrict__ S3,
    __half* __restrict__ D0, __half* __restrict__ D3)
{
    __shared__ float t[32][33];
    const int zz = blockIdx.z;
    const float* S = (zz == 0) ? S0 : (zz == 1) ? S1 : (zz == 2) ? S2 : S3;
    __half* D = (zz < 3) ? (D0 + (size_t)zz * 2048 * 2048) : D3;
    const int bx = blockIdx.x * 32, by = blockIdx.y * 32;
    const int lx = threadIdx.x & 31, ly = threadIdx.x >> 5;
#pragma unroll
    for (int i = 0; i < 32; i += 8)
        t[ly + i][lx] = S[(size_t)(by + ly + i) * 2048 + bx + lx];
    __syncthreads();
#pragma unroll
    for (int i = 0; i < 32; i += 8)
        D[(size_t)(bx + ly + i) * 2048 + by + lx] = __float2half(t[lx][ly + i]);
}

// ---------------- fused attention: flash softmax + linear memory + gated blend ----------------
// grid (qt=4 reversed, seg=8, bh=32), 256 threads, 2 CTAs/SM.
// All tensor-core fragments loaded via ldmatrix (gemm/pmat-validated patterns).
#define ATT2_SMEM (52224 * 2 + 512)

__global__ __launch_bounds__(256, 2) void attn_fused(
    const __half* __restrict__ QKVh,
    const float* __restrict__ Mpre, const float* __restrict__ zpre,
    const float* __restrict__ betas, __half* __restrict__ att)
{
    extern __shared__ __half smA[];
    __half* Qs = smA;
    const int tid = threadIdx.x;
    const int w = tid >> 5, lane = tid & 31;
    const int group = lane >> 2, tig = lane & 3;
    const int qt = 3 - blockIdx.x;
    const int seg = blockIdx.y, bh = blockIdx.z;
    const int b = bh >> 4, h = bh & 15;
    const int rowbase = b * 4096 + seg * 512;
    const int nj = 2 * qt + 2;

    // ldmatrix lane-address offsets (halves, stride 136)
    const int qa_off = (w * 16 + (lane & 15)) * 136 + ((lane >> 4) << 3);           // A, row-major
    const int kb_off = (((lane >> 4) << 3) + (lane & 7)) * 136 + (((lane >> 3) & 1) << 3); // B, K-major
    const int vb_row = (((lane >> 3) & 1) << 3) + (lane & 7);                        // B^T, [k][n]
    const int vb_col = (lane >> 4) << 3;

#pragma unroll
    for (int u = 0; u < 8; ++u) {
        int idx = tid + u * 256;
        int r = idx >> 4, c16 = idx & 15;
        cp16(smem_u32(Qs + r * 136 + c16 * 8),
             QKVh + (size_t)(rowbase + qt * 128 + r) * 6144 + h * 128 + c16 * 8);
    }
    {
        __half* Ks = smA + 17408;
        __half* Vs = smA + 34816;
#pragma unroll
        for (int u = 0; u < 4; ++u) {
            int idx = tid + u * 256;
            int r = idx >> 4, c16 = idx & 15;
            size_t gk = (size_t)(rowbase + r) * 6144 + h * 128 + c16 * 8;
            cp16(smem_u32(Ks + r * 136 + c16 * 8), QKVh + 2048 + gk);
            cp16(smem_u32(Vs + r * 136 + c16 * 8), QKVh + 4096 + gk);
        }
    }
    asm volatile("cp.async.commit_group;" ::: "memory");

    float o[16][4];
#pragma unroll
    for (int i = 0; i < 16; ++i)
#pragma unroll
        for (int j2 = 0; j2 < 4; ++j2) o[i][j2] = 0.f;
    float m0 = -1e30f, m1 = -1e30f, l0 = 0.f, l1 = 0.f;
    const float scale = 0.08838834764831845f;
    const int qg0 = qt * 128 + w * 16 + group;

    for (int j = 0; j < nj; ++j) {
        asm volatile("cp.async.wait_group 0;" ::: "memory");
        __syncthreads();
        if (j + 1 < nj) {
            __half* Ks = smA + 17408 + ((j + 1) & 1) * 8704;
            __half* Vs = smA + 34816 + ((j + 1) & 1) * 8704;
#pragma unroll
            for (int u = 0; u < 4; ++u) {
                int idx = tid + u * 256;
                int r = idx >> 4, c16 = idx & 15;
                size_t gk = (size_t)(rowbase + (j + 1) * 64 + r) * 6144 + h * 128 + c16 * 8;
                cp16(smem_u32(Ks + r * 136 + c16 * 8), QKVh + 2048 + gk);
                cp16(smem_u32(Vs + r * 136 + c16 * 8), QKVh + 4096 + gk);
            }
        }
        asm volatile("cp.async.commit_group;" ::: "memory");

        const int kmin = j * 64;
        if (kmin > qt * 128 + w * 16 + 15) continue;

        const __half* Ks = smA + 17408 + (j & 1) * 8704;
        const __half* Vs = smA + 34816 + (j & 1) * 8704;

        // ---- scores S[16,64] = Q @ K^T (ldmatrix fragments) ----
        float c[8][4];
#pragma unroll
        for (int nf = 0; nf < 8; ++nf)
#pragma unroll
            for (int i2 = 0; i2 < 4; ++i2) c[nf][i2] = 0.f;

#pragma unroll
        for (int kt = 0; kt < 8; ++kt) {
            uint32_t qa[4], kb[8][2];
            ldsm4(qa[0], qa[1], qa[2], qa[3], smem_u32(Qs + qa_off + kt * 16));
#pragma unroll
            for (int pr = 0; pr < 4; ++pr)
                ldsm4(kb[2 * pr][0], kb[2 * pr][1], kb[2 * pr + 1][0], kb[2 * pr + 1][1],
                      smem_u32(Ks + kb_off + pr * 16 * 136 + kt * 16));
#pragma unroll
            for (int nf = 0; nf < 8; ++nf)
                mma_f16(c[nf], qa, kb[nf]);
        }

#pragma unroll
        for (int nf = 0; nf < 8; ++nf)
#pragma unroll
            for (int i2 = 0; i2 < 4; ++i2) c[nf][i2] *= scale;
        if (kmin + 63 > qg0) {
#pragma unroll
            for (int nf = 0; nf < 8; ++nf) {
                const int kc = kmin + nf * 8 + tig * 2;
                if (kc > qg0)         c[nf][0] = -1e30f;
                if (kc + 1 > qg0)     c[nf][1] = -1e30f;
                if (kc > qg0 + 8)     c[nf][2] = -1e30f;
                if (kc + 1 > qg0 + 8) c[nf][3] = -1e30f;
            }
        }

        float rm0 = -1e30f, rm1 = -1e30f;
#pragma unroll
        for (int nf = 0; nf < 8; ++nf) {
            rm0 = fmaxf(rm0, fmaxf(c[nf][0], c[nf][1]));
            rm1 = fmaxf(rm1, fmaxf(c[nf][2], c[nf][3]));
        }
        rm0 = fmaxf(rm0, __shfl_xor_sync(0xffffffffu, rm0, 1));
        rm0 = fmaxf(rm0, __shfl_xor_sync(0xffffffffu, rm0, 2));
        rm1 = fmaxf(rm1, __shfl_xor_sync(0xffffffffu, rm1, 1));
        rm1 = fmaxf(rm1, __shfl_xor_sync(0xffffffffu, rm1, 2));
        const float mn0 = fmaxf(m0, rm0), mn1 = fmaxf(m1, rm1);
        const float sc0 = __expf(m0 - mn0), sc1 = __expf(m1 - mn1);
        float s0 = 0.f, s1 = 0.f;
#pragma unroll
        for (int nf = 0; nf < 8; ++nf) {
            c[nf][0] = __expf(c[nf][0] - mn0); s0 += c[nf][0];
            c[nf][1] = __expf(c[nf][1] - mn0); s0 += c[nf][1];
            c[nf][2] = __expf(c[nf][2] - mn1); s1 += c[nf][2];
            c[nf][3] = __expf(c[nf][3] - mn1); s1 += c[nf][3];
        }
        s0 += __shfl_xor_sync(0xffffffffu, s0, 1);
        s0 += __shfl_xor_sync(0xffffffffu, s0, 2);
        s1 += __shfl_xor_sync(0xffffffffu, s1, 1);
        s1 += __shfl_xor_sync(0xffffffffu, s1, 2);
        l0 = l0 * sc0 + s0; l1 = l1 * sc1 + s1;
        m0 = mn0; m1 = mn1;
#pragma unroll
        for (int vf = 0; vf < 16; ++vf) {
            o[vf][0] *= sc0; o[vf][1] *= sc0;
            o[vf][2] *= sc1; o[vf][3] *= sc1;
        }

        // ---- O += P @ V (ldsm4t B fragments, pmat pattern) ----
#pragma unroll
        for (int kt2 = 0; kt2 < 4; ++kt2) {
            uint32_t pa[4];
            pa[0] = packh2(c[2 * kt2][0],     c[2 * kt2][1]);
            pa[1] = packh2(c[2 * kt2][2],     c[2 * kt2][3]);
            pa[2] = packh2(c[2 * kt2 + 1][0], c[2 * kt2 + 1][1]);
            pa[3] = packh2(c[2 * kt2 + 1][2], c[2 * kt2 + 1][3]);
#pragma unroll
            for (int np = 0; np < 8; ++np) {
                uint32_t vb0[2], vb1[2];
                ldsm4t(vb0[0], vb0[1], vb1[0], vb1[1],
                       smem_u32(&Vs[(kt2 * 16 + vb_row) * 136 + np * 16 + vb_col]));
                mma_f16(o[2 * np], pa, vb0);
                mma_f16(o[2 * np + 1], pa, vb1);
            }
        }
    }

    // ======== fused linear-memory epilogue ========
    asm volatile("cp.async.wait_group 0;" ::: "memory");
    __syncthreads();                       // all warps done with Ks/Vs

    __half* sigq = smA + 17408;            // recycle Ks double-buffer
    __half* Mh   = smA + 34816;            // recycle Vs double-buffer
    float* zsm = (float*)(smA + 52224);    // 128 floats

    // sig_q = elu(Qs)+1 (half), M tile fp32 -> half
    {
        const float* Mg = Mpre + ((size_t)bh * 8 + seg) * 16384;
#pragma unroll
        for (int u = 0; u < 8; ++u) {
            int idx = tid + u * 256;
            int r = idx >> 4, c8 = (idx & 15) << 3;
            uint4 q4 = *(const uint4*)&Qs[r * 136 + c8];
            const __half* qh = (const __half*)&q4;
            __half2 qo[4];
#pragma unroll
            for (int i = 0; i < 4; ++i)
                qo[i] = __floats2half2_rn(elu1(__half2float(qh[2 * i])),
                                          elu1(__half2float(qh[2 * i + 1])));
            *(uint4*)&sigq[r * 136 + c8] = *(uint4*)qo;

            float4 mv0 = *(const float4*)&Mg[r * 128 + c8];
            float4 mv1 = *(const float4*)&Mg[r * 128 + c8 + 4];
            __half2 mo[4] = {
                __floats2half2_rn(mv0.x, mv0.y), __floats2half2_rn(mv0.z, mv0.w),
                __floats2half2_rn(mv1.x, mv1.y), __floats2half2_rn(mv1.z, mv1.w)
            };
            *(uint4*)&Mh[r * 136 + c8] = *(uint4*)mo;
        }
        if (tid < 128) zsm[tid] = zpre[((size_t)bh * 8 + seg) * 128 + tid];
    }
    __syncthreads();

    // stage normalized softmax output to Qs region (frees o[] registers)
    const int r0 = w * 16 + group;
    {
        const float inv0 = 1.f / l0, inv1 = 1.f / l1;
#pragma unroll
        for (int vf = 0; vf < 16; ++vf) {
            const int dv = vf * 8 + tig * 2;
            *(__half2*)&Qs[r0 * 136 + dv] =
                __floats2half2_rn(o[vf][0] * inv0, o[vf][1] * inv0);
            *(__half2*)&Qs[(r0 + 8) * 136 + dv] =
                __floats2half2_rn(o[vf][2] * inv1, o[vf][3] * inv1);
        }
    }

    // om = sig_q @ M  (gemm A-pattern + pmat B-pattern)
    float om[16][4];
#pragma unroll
    for (int i = 0; i < 16; ++i)
#pragma unroll
        for (int j2 = 0; j2 < 4; ++j2) om[i][j2] = 0.f;

#pragma unroll
    for (int ks = 0; ks < 8; ++ks) {
        uint32_t af[4];
        ldsm4(af[0], af[1], af[2], af[3], smem_u32(sigq + qa_off + ks * 16));
#pragma unroll
        for (int nf2 = 0; nf2 < 8; ++nf2) {
            uint32_t bf0[2], bf1[2];
            ldsm4t(bf0[0], bf0[1], bf1[0], bf1[1],
                   smem_u32(&Mh[(ks * 16 + vb_row) * 136 + nf2 * 16 + vb_col]));
            mma_f16(om[2 * nf2], af, bf0);
            mma_f16(om[2 * nf2 + 1], af, bf1);
        }
    }

    // denominator: sig_q . z (fp32, tig-split + shfl)
    float den0 = 0.f, den1 = 0.f;
#pragma unroll 8
    for (int d = tig * 32; d < tig * 32 + 32; ++d) {
        float zd = zsm[d];
        den0 += __half2float(sigq[r0 * 136 + d]) * zd;
        den1 += __half2float(sigq[(r0 + 8) * 136 + d]) * zd;
    }
    den0 += __shfl_xor_sync(0xffffffffu, den0, 1);
    den0 += __shfl_xor_sync(0xffffffffu, den0, 2);
    den1 += __shfl_xor_sync(0xffffffffu, den1, 1);
    den1 += __shfl_xor_sync(0xffffffffu, den1, 2);
    const float invd0 = 1.f / den0, invd1 = 1.f / den1;

    // gated blend (staged softmax from smem) + store
    const int grow0 = rowbase + qt * 128 + r0;
#pragma unroll
    for (int vf = 0; vf < 16; ++vf) {
        const int dv = vf * 8 + tig * 2;
        float g0 = 1.f / (1.f + __expf(-betas[h * 128 + dv]));
        float g1 = 1.f / (1.f + __expf(-betas[h * 128 + dv + 1]));
        __half2 so0 = *(const __half2*)&Qs[r0 * 136 + dv];
        __half2 so1 = *(const __half2*)&Qs[(r0 + 8) * 136 + dv];
        const size_t base0 = (size_t)grow0 * 2048 + h * 128 + dv;
        const size_t base1 = (size_t)(grow0 + 8) * 2048 + h * 128 + dv;
        *(__half2*)&att[base0] = __floats2half2_rn(
            g0 * (om[vf][0] * invd0) + (1.f - g0) * __half2float(so0.x),
            g1 * (om[vf][1] * invd0) + (1.f - g1) * __half2float(so0.y));
        *(__half2*)&att[base1] = __floats2half2_rn(
            g0 * (om[vf][2] * invd1) + (1.f - g0) * __half2float(so1.x),
            g1 * (om[vf][3] * invd1) + (1.f - g1) * __half2float(so1.y));
    }
}

// ---------------- per-segment memory outer product: tensor cores + fused z sums ----------------
__global__ __launch_bounds__(256, 2) void pmat_k(
    const __half* __restrict__ Kg, const __half* __restrict__ Vg,
    float* __restrict__ P, float* __restrict__ z)
{
    __shared__ __half skh[32 * 136];
    __shared__ __half svh[32 * 136];
    const int tid = threadIdx.x;
    const int wid = tid >> 5, lane = tid & 31;
    const int group = lane >> 2, tig = lane & 3;
    const int wm = wid >> 2, wn = wid & 3;
    const int seg = blockIdx.x, bh = blockIdx.y;
    const int b = bh >> 4, h = bh & 15;
    const int rowbase = b * 4096 + seg * 512;

    float acc[4][4][4] = {};
    float zacc = 0.f;

    const int arow = ((lane >> 4) << 3) + (lane & 7);
    const int acolo = ((lane >> 3) & 1) << 3;
    const int brow = (((lane >> 3) & 1) << 3) + (lane & 7);
    const int bcolo = (lane >> 4) << 3;

    for (int ck = 0; ck < 512; ck += 32) {
        __syncthreads();
#pragma unroll
        for (int u = 0; u < 2; ++u) {
            const int idx = tid + u * 256;
            const int r = idx >> 4;
            const int c8 = (idx & 15) << 3;
            const size_t gi = (size_t)(rowbase + ck + r) * 6144 + h * 128 + c8;
            uint4 k4 = *(const uint4*)&Kg[gi];
            const __half* kh = (const __half*)&k4;
            __half2 ko[4];
#pragma unroll
            for (int i = 0; i < 4; ++i)
                ko[i] = __floats2half2_rn(elu1(__half2float(kh[2 * i])),
                                          elu1(__half2float(kh[2 * i + 1])));
            *(uint4*)&skh[r * 136 + c8] = *(uint4*)ko;
            *(uint4*)&svh[r * 136 + c8] = *(const uint4*)&Vg[gi];
        }
        __syncthreads();

        if (tid < 128) {
#pragma unroll
            for (int s = 0; s < 32; ++s) zacc += __half2float(skh[s * 136 + tid]);
        }

#pragma unroll
        for (int kstep = 0; kstep < 2; ++kstep) {
            const int k0 = kstep * 16;
            uint32_t af[4][4], bf[4][2];
#pragma unroll
            for (int mf = 0; mf < 4; ++mf)
                ldsm4t(af[mf][0], af[mf][1], af[mf][2], af[mf][3],
                       smem_u32(&skh[(k0 + arow) * 136 + wm * 64 + mf * 16 + acolo]));
#pragma unroll
            for (int np = 0; np < 2; ++np)
                ldsm4t(bf[2 * np][0], bf[2 * np][1], bf[2 * np + 1][0], bf[2 * np + 1][1],
                       smem_u32(&svh[(k0 + brow) * 136 + wn * 32 + np * 16 + bcolo]));
#pragma unroll
            for (int mf = 0; mf < 4; ++mf)
#pragma unroll
                for (int nf = 0; nf < 4; ++nf)
                    mma_f16(acc[mf][nf], af[mf], bf[nf]);
        }
    }

    float* Pp = P + ((size_t)bh * 8 + seg) * 16384;
#pragma unroll
    for (int mf = 0; mf < 4; ++mf) {
        const int row = wm * 64 + mf * 16 + group;
#pragma unroll
        for (int nf = 0; nf < 4; ++nf) {
            const int col = wn * 32 + nf * 8 + 2 * tig;
            *(float2*)&Pp[row * 128 + col] = make_float2(acc[mf][nf][0], acc[mf][nf][1]);
            *(float2*)&Pp[(row + 8) * 128 + col] = make_float2(acc[mf][nf][2], acc[mf][nf][3]);
        }
    }
    if (tid < 128)
        z[((size_t)bh * 8 + seg) * 128 + tid] = zacc;
}

// ---------------- exclusive prefix over segments (grid 32x8) ----------------
__global__ void prefix_k(const float* __restrict__ P, const float* __restrict__ z,
                         float* __restrict__ Mpre, float* __restrict__ zpre)
{
    const int bh = blockIdx.x;
    const int part = blockIdx.y;
    const int tid = threadIdx.x;
    const int i0 = part * 2048;
    for (int idx = i0 + tid; idx < i0 + 2048; idx += 256) {
        float run = 0.f;
        for (int s = 0; s < 8; ++s) {
            size_t o = ((size_t)bh * 8 + s) * 16384 + idx;
            Mpre[o] = run;
            run += P[o];
        }
    }
    if (part == 0 && tid < 128) {
        float run = 1.f / 128.f;
        for (int s = 0; s < 8; ++s) {
            size_t o = ((size_t)bh * 8 + s) * 128 + tid;
            zpre[o] = run;
            run += z[o];
        }
    }
}

// ---------------- residual + LayerNorm (vectorized, smem row cache) ----------------
__global__ __launch_bounds__(256) void ln_k(
    const float* __restrict__ y, const float* __restrict__ x,
    const float* __restrict__ gm, const float* __restrict__ bt,
    float* __restrict__ out)
{
    __shared__ float buf[2048];
    __shared__ float r1[8], r2[8];
    const int row = blockIdx.x, tid = threadIdx.x;
    const float* yp = y + (size_t)row * 2048;
    const float* xp = x + (size_t)row * 2048;
    float s1 = 0.f, s2 = 0.f;
#pragma unroll
    for (int u = 0; u < 2; ++u) {
        const int c = (tid + u * 256) * 4;
        float4 yv = *(const float4*)&yp[c];
        float4 xv = *(const float4*)&xp[c];
        float4 v = make_float4(yv.x + xv.x, yv.y + xv.y, yv.z + xv.z, yv.w + xv.w);
        *(float4*)&buf[c] = v;
        s1 += v.x + v.y + v.z + v.w;
        s2 += v.x * v.x + v.y * v.y + v.z * v.z + v.w * v.w;
    }
#pragma unroll
    for (int off = 16; off >= 1; off >>= 1) {
        s1 += __shfl_xor_sync(0xffffffffu, s1, off);
        s2 += __shfl_xor_sync(0xffffffffu, s2, off);
    }
    if ((tid & 31) == 0) { r1[tid >> 5] = s1; r2[tid >> 5] = s2; }
    __syncthreads();
    if (tid == 0) {
        float a = 0.f, bb = 0.f;
        for (int w = 0; w < 8; ++w) { a += r1[w]; bb += r2[w]; }
        r1[0] = a; r2[0] = bb;
    }
    __syncthreads();
    const float mu = r1[0] * (1.f / 2048.f);
    const float var = r2[0] * (1.f / 2048.f) - mu * mu;
    const float rs = rsqrtf(var + 1e-5f);
#pragma unroll
    for (int u = 0; u < 2; ++u) {
        const int c = (tid + u * 256) * 4;
        float4 v = *(const float4*)&buf[c];
        float4 g = *(const float4*)&gm[c];
        float4 bb = *(const float4*)&bt[c];
        float4 oo;
        oo.x = (v.x - mu) * rs * g.x + bb.x;
        oo.y = (v.y - mu) * rs * g.y + bb.y;
        oo.z = (v.z - mu) * rs * g.z + bb.z;
        oo.w = (v.w - mu) * rs * g.w + bb.w;
        *(float4*)&out[(size_t)row * 2048 + c] = oo;
    }
}

// ---------------- host ----------------
extern "C" void kernel_launch(void* const* d_in, const int* in_sizes, int n_in,
                              void* d_out, int out_size)
{
    const float* x     = (const float*)d_in[0];
    const float* Wq    = (const float*)d_in[1];
    const float* Wk    = (const float*)d_in[2];
    const float* Wv    = (const float*)d_in[3];
    const float* Wo    = (const float*)d_in[4];
    const float* betas = (const float*)d_in[5];
    const float* W1    = (const float*)d_in[6];
    const float* b1    = (const float*)d_in[7];
    const float* W2    = (const float*)d_in[8];
    const float* b2    = (const float*)d_in[9];
    const float* lng   = (const float*)d_in[10];
    const float* lnb   = (const float*)d_in[11];
    float* out = (float*)d_out;

    float *Pb, *Mp, *zb, *zp, *YB;
    __half *QKV, *XH, *AT, *AO, *HB, *WqkvT, *WoT, *W1T, *W2T;
    cudaGetSymbolAddress((void**)&QKV, g_qkv);
    cudaGetSymbolAddress((void**)&XH, g_xh);
    cudaGetSymbolAddress((void**)&AT, g_att);
    cudaGetSymbolAddress((void**)&Pb, g_P);
    cudaGetSymbolAddress((void**)&Mp, g_Mpre);
    cudaGetSymbolAddress((void**)&zb, g_zz);
    cudaGetSymbolAddress((void**)&zp, g_zpre);
    cudaGetSymbolAddress((void**)&AO, g_ao);
    cudaGetSymbolAddress((void**)&HB, g_hb);
    cudaGetSymbolAddress((void**)&YB, g_yb);
    cudaGetSymbolAddress((void**)&WqkvT, g_WqkvT);
    cudaGetSymbolAddress((void**)&WoT, g_WoT);
    cudaGetSymbolAddress((void**)&W1T, g_W1T);
    cudaGetSymbolAddress((void**)&W2T, g_W2T);

    const __half* Kb = QKV + 2048;

    cudaFuncSetAttribute(attn_fused, cudaFuncAttributeMaxDynamicSharedMemorySize, ATT2_SMEM);
    cudaFuncSetAttribute((const void*)gemm_mma<false, false, __half>, cudaFuncAttributeMaxDynamicSharedMemorySize, GEMM_SMEM);
    cudaFuncSetAttribute((const void*)gemm_mma<true, true, __half>,   cudaFuncAttributeMaxDynamicSharedMemorySize, GEMM_SMEM);
    cudaFuncSetAttribute((const void*)gemm_mma<true, false, float>,   cudaFuncAttributeMaxDynamicSharedMemorySize, GEMM_SMEM);

    // ---- input convert + weight transposes ----
    cvt_h<<<8192, 256>>>(x, XH);
    transpose4_h<<<dim3(64, 64, 4), 256>>>(Wq, Wk, Wv, Wo, WqkvT, WoT);
    transpose_h<<<dim3(256, 64), 256>>>(W1, W1T, 2048, 8192);
    transpose_h<<<dim3(64, 256), 256>>>(W2, W2T, 8192, 2048);

    // ---- fused QKV projection (half out) ----
    gemm_mma<false, false, __half><<<dim3(48, 64), 256, GEMM_SMEM>>>(XH, WqkvT, nullptr, QKV, 6144, 2048);

    // ---- linear memory path first (attn_fused consumes Mpre/zpre) ----
    dim3 gz(8, 32);
    pmat_k<<<gz, 256>>>(Kb, QKV + 4096, Pb, zb);
    prefix_k<<<dim3(32, 8), 256>>>(Pb, zb, Mp, zp);

    // ---- fused attention (softmax + memory + blend) ----
    attn_fused<<<dim3(4, 8, 32), 256, ATT2_SMEM>>>(QKV, Mp, zp, betas, AT);

    // ---- output projection + MLP ----
    gemm_mma<false, false, __half><<<dim3(16, 64), 256, GEMM_SMEM>>>(AT, WoT, nullptr, AO, 2048, 2048);
    gemm_mma<true, true, __half><<<dim3(64, 64), 256, GEMM_SMEM>>>(AO, W1T, b1, HB, 8192, 2048);
    gemm_mma<true, false, float><<<dim3(16, 64), 256, GEMM_SMEM>>>(HB, W2T, b2, YB, 2048, 8192);

    // ---- residual + LayerNorm ----
    ln_k<<<8192, 256>>>(YB, x, lng, lnb, out);
}

// round 17
// speedup vs baseline: 1.5223x; 1.5223x over previous
#include <cuda_runtime.h>
#include <cuda_fp16.h>
#include <math.h>
#include <stdint.h>

// ---------------- shapes ----------------
// B=2, S=4096, D=2048, H=16, DK=DV=128, SEG=512, NSEG=8, DH=8192, M=B*S=8192
// QKV fused (half): stride 6144 (Q at col 0, K at 2048, V at 4096)

// ---------------- scratch ----------------
static __device__ __half g_qkv[8192 * 6144];
static __device__ __half g_xh[8192 * 2048];
static __device__ __half g_att[8192 * 2048];
static __device__ float  g_P[2 * 16 * 8 * 128 * 128];
static __device__ float  g_Mpre[2 * 16 * 8 * 128 * 128];
static __device__ float  g_zz[2 * 16 * 8 * 128];
static __device__ float  g_zpre[2 * 16 * 8 * 128];
static __device__ __half g_ao[8192 * 2048];
static __device__ __half g_hb[8192 * 8192];
static __device__ float  g_yb[8192 * 2048];
static __device__ __half g_WqkvT[6144 * 2048];
static __device__ __half g_WoT[2048 * 2048];
static __device__ __half g_W1T[8192 * 2048];
static __device__ __half g_W2T[2048 * 8192];

// ---------------- helpers ----------------
__device__ __forceinline__ uint32_t smem_u32(const void* p) {
    uint32_t a;
    asm("{ .reg .u64 t; cvta.to.shared.u64 t, %1; cvt.u32.u64 %0, t; }" : "=r"(a) : "l"(p));
    return a;
}
__device__ __forceinline__ void cp16(uint32_t dst, const void* src) {
    asm volatile("cp.async.cg.shared.global [%0], [%1], 16;" :: "r"(dst), "l"(src) : "memory");
}
__device__ __forceinline__ void mma_f16(float* c, const uint32_t* a, const uint32_t* b) {
    asm volatile("mma.sync.aligned.m16n8k16.row.col.f32.f16.f16.f32 "
        "{%0,%1,%2,%3}, {%4,%5,%6,%7}, {%8,%9}, {%0,%1,%2,%3};"
        : "+f"(c[0]), "+f"(c[1]), "+f"(c[2]), "+f"(c[3])
        : "r"(a[0]), "r"(a[1]), "r"(a[2]), "r"(a[3]), "r"(b[0]), "r"(b[1]));
}
__device__ __forceinline__ void ldsm4(uint32_t& r0, uint32_t& r1, uint32_t& r2, uint32_t& r3,
                                      uint32_t addr) {
    asm volatile("ldmatrix.sync.aligned.m8n8.x4.shared.b16 {%0,%1,%2,%3}, [%4];"
        : "=r"(r0), "=r"(r1), "=r"(r2), "=r"(r3) : "r"(addr));
}
__device__ __forceinline__ void ldsm4t(uint32_t& r0, uint32_t& r1, uint32_t& r2, uint32_t& r3,
                                       uint32_t addr) {
    asm volatile("ldmatrix.sync.aligned.m8n8.x4.trans.shared.b16 {%0,%1,%2,%3}, [%4];"
        : "=r"(r0), "=r"(r1), "=r"(r2), "=r"(r3) : "r"(addr));
}
__device__ __forceinline__ uint32_t packh2(float a, float b) {
    __half2 h = __floats2half2_rn(a, b);
    return *(uint32_t*)&h;
}
__device__ __forceinline__ float elu1(float x) {
    return x > 0.f ? x + 1.f : __expf(x);
}

// ---------------- fp16 tensor-core GEMM (128x128, BK=64, 3-stage, single-barrier) ----------------
#define GROWS 72
#define GSTAGE_H (128 * GROWS * 2)
#define GEMM_SMEM (3 * GSTAGE_H * 2)

template <bool BIAS, bool RELU, typename OUTT>
__global__ __launch_bounds__(256, 2) void gemm_mma(
    const __half* __restrict__ A, const __half* __restrict__ Bt,
    const float* __restrict__ bias, OUTT* __restrict__ C,
    int Nn, int K)
{
    extern __shared__ __half smh[];
    const int tid = threadIdx.x;
    const int wid = tid >> 5, lane = tid & 31;
    const int group = lane >> 2, tig = lane & 3;
    const int wm = wid >> 2, wn = wid & 3;
    const int m0 = blockIdx.y * 128, n0 = blockIdx.x * 128;
    const int nt = K >> 6;

    const int lrow = tid >> 3;
    const int lc   = (tid & 7) << 3;

    const int a_off = (wm * 64 + (lane & 15)) * GROWS + ((lane >> 4) << 3);
    const int b_off = (wn * 32 + ((lane >> 4) << 3) + (lane & 7)) * GROWS + (((lane >> 3) & 1) << 3);

#pragma unroll
    for (int t = 0; t < 2; ++t) {
        __half* As = smh + t * GSTAGE_H;
        __half* Bs = As + 128 * GROWS;
        const int k0 = t * 64;
#pragma unroll
        for (int j = 0; j < 4; ++j) {
            int row = lrow + j * 32;
            cp16(smem_u32(As + row * GROWS + lc), A + (size_t)(m0 + row) * K + k0 + lc);
            cp16(smem_u32(Bs + row * GROWS + lc), Bt + (size_t)(n0 + row) * K + k0 + lc);
        }
        asm volatile("cp.async.commit_group;" ::: "memory");
    }

    float acc[4][4][4] = {};

    for (int t = 0; t < nt; ++t) {
        asm volatile("cp.async.wait_group 1;" ::: "memory");
        __syncthreads();

        const __half* As = smh + (t % 3) * GSTAGE_H;
        const __half* Bs = As + 128 * GROWS;

#pragma unroll
        for (int ks = 0; ks < 4; ++ks) {
            uint32_t af[4][4], bf[4][2];
#pragma unroll
            for (int mf = 0; mf < 4; ++mf)
                ldsm4(af[mf][0], af[mf][1], af[mf][2], af[mf][3],
                      smem_u32(As + a_off + mf * 16 * GROWS + ks * 16));
#pragma unroll
            for (int pr = 0; pr < 2; ++pr)
                ldsm4(bf[2 * pr][0], bf[2 * pr][1], bf[2 * pr + 1][0], bf[2 * pr + 1][1],
                      smem_u32(Bs + b_off + pr * 16 * GROWS + ks * 16));
#pragma unroll
            for (int mf = 0; mf < 4; ++mf)
#pragma unroll
                for (int nf = 0; nf < 4; ++nf)
                    mma_f16(acc[mf][nf], af[mf], bf[nf]);
        }

        if (t + 2 < nt) {
            const int s = (t + 2) % 3;
            __half* Asw = smh + s * GSTAGE_H;
            __half* Bsw = Asw + 128 * GROWS;
            const int k0 = (t + 2) * 64;
#pragma unroll
            for (int j = 0; j < 4; ++j) {
                int row = lrow + j * 32;
                cp16(smem_u32(Asw + row * GROWS + lc), A + (size_t)(m0 + row) * K + k0 + lc);
                cp16(smem_u32(Bsw + row * GROWS + lc), Bt + (size_t)(n0 + row) * K + k0 + lc);
            }
        }
        asm volatile("cp.async.commit_group;" ::: "memory");
    }

#pragma unroll
    for (int mf = 0; mf < 4; ++mf) {
        const int row = m0 + wm * 64 + mf * 16 + group;
#pragma unroll
        for (int nf = 0; nf < 4; ++nf) {
            const int col = n0 + wn * 32 + nf * 8 + 2 * tig;
            float2 v0 = make_float2(acc[mf][nf][0], acc[mf][nf][1]);
            float2 v1 = make_float2(acc[mf][nf][2], acc[mf][nf][3]);
            if (BIAS) {
                float b0 = bias[col], b1 = bias[col + 1];
                v0.x += b0; v0.y += b1; v1.x += b0; v1.y += b1;
            }
            if (RELU) {
                v0.x = fmaxf(v0.x, 0.f); v0.y = fmaxf(v0.y, 0.f);
                v1.x = fmaxf(v1.x, 0.f); v1.y = fmaxf(v1.y, 0.f);
            }
            if constexpr (sizeof(OUTT) == 4) {
                *(float2*)&C[(size_t)row * Nn + col] = v0;
                *(float2*)&C[(size_t)(row + 8) * Nn + col] = v1;
            } else {
                *(__half2*)&C[(size_t)row * Nn + col] = __floats2half2_rn(v0.x, v0.y);
                *(__half2*)&C[(size_t)(row + 8) * Nn + col] = __floats2half2_rn(v1.x, v1.y);
            }
        }
    }
}

// ---------------- fp32 -> fp16 convert ----------------
__global__ __launch_bounds__(256) void cvt_h(const float* __restrict__ S, __half* __restrict__ D)
{
    const size_t i = ((size_t)blockIdx.x * 256 + threadIdx.x) * 8;
    float4 a = *(const float4*)&S[i];
    float4 b = *(const float4*)&S[i + 4];
    __half2 h[4] = {
        __floats2half2_rn(a.x, a.y), __floats2half2_rn(a.z, a.w),
        __floats2half2_rn(b.x, b.y), __floats2half2_rn(b.z, b.w)
    };
    *(uint4*)&D[i] = *(uint4*)h;
}

// ---------------- weight transpose -> fp16 ----------------
__global__ __launch_bounds__(256) void transpose_h(
    const float* __restrict__ S, __half* __restrict__ D, int R, int C)
{
    __shared__ float t[32][33];
    const int bx = blockIdx.x * 32, by = blockIdx.y * 32;
    const int lx = threadIdx.x & 31, ly = threadIdx.x >> 5;
#pragma unroll
    for (int i = 0; i < 32; i += 8)
        t[ly + i][lx] = S[(size_t)(by + ly + i) * C + bx + lx];
    __syncthreads();
#pragma unroll
    for (int i = 0; i < 32; i += 8)
        D[(size_t)(bx + ly + i) * R + by + lx] = __float2half(t[lx][ly + i]);
}

// 4-way merged 2048x2048 transpose
__global__ __launch_bounds__(256) void transpose4_h(
    const float* __restrict__ S0, const float* __restrict__ S1,
    const float* __restrict__ S2, const float* __restrict__ S3,
    __half* __restrict__ D0, __half* __restrict__ D3)
{
    __shared__ float t[32][33];
    const int zz = blockIdx.z;
    const float* S = (zz == 0) ? S0 : (zz == 1) ? S1 : (zz == 2) ? S2 : S3;
    __half* D = (zz < 3) ? (D0 + (size_t)zz * 2048 * 2048) : D3;
    const int bx = blockIdx.x * 32, by = blockIdx.y * 32;
    const int lx = threadIdx.x & 31, ly = threadIdx.x >> 5;
#pragma unroll
    for (int i = 0; i < 32; i += 8)
        t[ly + i][lx] = S[(size_t)(by + ly + i) * 2048 + bx + lx];
    __syncthreads();
#pragma unroll
    for (int i = 0; i < 32; i += 8)
        D[(size_t)(bx + ly + i) * 2048 + by + lx] = __float2half(t[lx][ly + i]);
}

// ---------------- fused attention: flash softmax + linear memory + gated blend ----------------
// grid (qt=4 reversed, seg=8, bh=32), 256 threads, 2 CTAs/SM.
// Scalar fragment loads (narrow live sets; ldmatrix batching spills under the 2-CTA reg clamp).
#define ATT2_SMEM (52224 * 2 + 512)

__global__ __launch_bounds__(256, 2) void attn_fused(
    const __half* __restrict__ QKVh,
    const float* __restrict__ Mpre, const float* __restrict__ zpre,
    const float* __restrict__ betas, __half* __restrict__ att)
{
    extern __shared__ __half smA[];
    __half* Qs = smA;
    const int tid = threadIdx.x;
    const int w = tid >> 5, lane = tid & 31;
    const int group = lane >> 2, tig = lane & 3;
    const int qt = 3 - blockIdx.x;
    const int seg = blockIdx.y, bh = blockIdx.z;
    const int b = bh >> 4, h = bh & 15;
    const int rowbase = b * 4096 + seg * 512;
    const int nj = 2 * qt + 2;

#pragma unroll
    for (int u = 0; u < 8; ++u) {
        int idx = tid + u * 256;
        int r = idx >> 4, c16 = idx & 15;
        cp16(smem_u32(Qs + r * 136 + c16 * 8),
             QKVh + (size_t)(rowbase + qt * 128 + r) * 6144 + h * 128 + c16 * 8);
    }
    {
        __half* Ks = smA + 17408;
        __half* Vs = smA + 34816;
#pragma unroll
        for (int u = 0; u < 4; ++u) {
            int idx = tid + u * 256;
            int r = idx >> 4, c16 = idx & 15;
            size_t gk = (size_t)(rowbase + r) * 6144 + h * 128 + c16 * 8;
            cp16(smem_u32(Ks + r * 136 + c16 * 8), QKVh + 2048 + gk);
            cp16(smem_u32(Vs + r * 136 + c16 * 8), QKVh + 4096 + gk);
        }
    }
    asm volatile("cp.async.commit_group;" ::: "memory");

    float o[16][4];
#pragma unroll
    for (int i = 0; i < 16; ++i)
#pragma unroll
        for (int j2 = 0; j2 < 4; ++j2) o[i][j2] = 0.f;
    float m0 = -1e30f, m1 = -1e30f, l0 = 0.f, l1 = 0.f;
    const float scale = 0.08838834764831845f;
    const int qg0 = qt * 128 + w * 16 + group;

    for (int j = 0; j < nj; ++j) {
        asm volatile("cp.async.wait_group 0;" ::: "memory");
        __syncthreads();
        if (j + 1 < nj) {
            __half* Ks = smA + 17408 + ((j + 1) & 1) * 8704;
            __half* Vs = smA + 34816 + ((j + 1) & 1) * 8704;
#pragma unroll
            for (int u = 0; u < 4; ++u) {
                int idx = tid + u * 256;
                int r = idx >> 4, c16 = idx & 15;
                size_t gk = (size_t)(rowbase + (j + 1) * 64 + r) * 6144 + h * 128 + c16 * 8;
                cp16(smem_u32(Ks + r * 136 + c16 * 8), QKVh + 2048 + gk);
                cp16(smem_u32(Vs + r * 136 + c16 * 8), QKVh + 4096 + gk);
            }
        }
        asm volatile("cp.async.commit_group;" ::: "memory");

        const int kmin = j * 64;
        if (kmin > qt * 128 + w * 16 + 15) continue;

        const __half* Ks = smA + 17408 + (j & 1) * 8704;
        const __half* Vs = smA + 34816 + (j & 1) * 8704;

        float c[8][4];
#pragma unroll
        for (int nf = 0; nf < 8; ++nf)
#pragma unroll
            for (int i2 = 0; i2 < 4; ++i2) c[nf][i2] = 0.f;

#pragma unroll
        for (int kt = 0; kt < 8; ++kt) {
            uint32_t qa[4];
            const int qr = w * 16 + group;
            const int qc = kt * 16 + tig * 2;
            qa[0] = *(const uint32_t*)&Qs[qr * 136 + qc];
            qa[1] = *(const uint32_t*)&Qs[(qr + 8) * 136 + qc];
            qa[2] = *(const uint32_t*)&Qs[qr * 136 + qc + 8];
            qa[3] = *(const uint32_t*)&Qs[(qr + 8) * 136 + qc + 8];
#pragma unroll
            for (int nf = 0; nf < 8; ++nf) {
                uint32_t kb[2];
                const int kr = nf * 8 + group;
                kb[0] = *(const uint32_t*)&Ks[kr * 136 + qc];
                kb[1] = *(const uint32_t*)&Ks[kr * 136 + qc + 8];
                mma_f16(c[nf], qa, kb);
            }
        }

#pragma unroll
        for (int nf = 0; nf < 8; ++nf)
#pragma unroll
            for (int i2 = 0; i2 < 4; ++i2) c[nf][i2] *= scale;
        if (kmin + 63 > qg0) {
#pragma unroll
            for (int nf = 0; nf < 8; ++nf) {
                const int kc = kmin + nf * 8 + tig * 2;
                if (kc > qg0)         c[nf][0] = -1e30f;
                if (kc + 1 > qg0)     c[nf][1] = -1e30f;
                if (kc > qg0 + 8)     c[nf][2] = -1e30f;
                if (kc + 1 > qg0 + 8) c[nf][3] = -1e30f;
            }
        }

        float rm0 = -1e30f, rm1 = -1e30f;
#pragma unroll
        for (int nf = 0; nf < 8; ++nf) {
            rm0 = fmaxf(rm0, fmaxf(c[nf][0], c[nf][1]));
            rm1 = fmaxf(rm1, fmaxf(c[nf][2], c[nf][3]));
        }
        rm0 = fmaxf(rm0, __shfl_xor_sync(0xffffffffu, rm0, 1));
        rm0 = fmaxf(rm0, __shfl_xor_sync(0xffffffffu, rm0, 2));
        rm1 = fmaxf(rm1, __shfl_xor_sync(0xffffffffu, rm1, 1));
        rm1 = fmaxf(rm1, __shfl_xor_sync(0xffffffffu, rm1, 2));
        const float mn0 = fmaxf(m0, rm0), mn1 = fmaxf(m1, rm1);
        const float sc0 = __expf(m0 - mn0), sc1 = __expf(m1 - mn1);
        float s0 = 0.f, s1 = 0.f;
#pragma unroll
        for (int nf = 0; nf < 8; ++nf) {
            c[nf][0] = __expf(c[nf][0] - mn0); s0 += c[nf][0];
            c[nf][1] = __expf(c[nf][1] - mn0); s0 += c[nf][1];
            c[nf][2] = __expf(c[nf][2] - mn1); s1 += c[nf][2];
            c[nf][3] = __expf(c[nf][3] - mn1); s1 += c[nf][3];
        }
        s0 += __shfl_xor_sync(0xffffffffu, s0, 1);
        s0 += __shfl_xor_sync(0xffffffffu, s0, 2);
        s1 += __shfl_xor_sync(0xffffffffu, s1, 1);
        s1 += __shfl_xor_sync(0xffffffffu, s1, 2);
        l0 = l0 * sc0 + s0; l1 = l1 * sc1 + s1;
        m0 = mn0; m1 = mn1;
#pragma unroll
        for (int vf = 0; vf < 16; ++vf) {
            o[vf][0] *= sc0; o[vf][1] *= sc0;
            o[vf][2] *= sc1; o[vf][3] *= sc1;
        }

#pragma unroll
        for (int kt2 = 0; kt2 < 4; ++kt2) {
            uint32_t pa[4];
            pa[0] = packh2(c[2 * kt2][0],     c[2 * kt2][1]);
            pa[1] = packh2(c[2 * kt2][2],     c[2 * kt2][3]);
            pa[2] = packh2(c[2 * kt2 + 1][0], c[2 * kt2 + 1][1]);
            pa[3] = packh2(c[2 * kt2 + 1][2], c[2 * kt2 + 1][3]);
            const int kv0 = kt2 * 16 + tig * 2;
#pragma unroll
            for (int vf = 0; vf < 16; ++vf) {
                const int dv = vf * 8 + group;
                __half2 t0, t1;
                t0.x = Vs[kv0 * 136 + dv];
                t0.y = Vs[(kv0 + 1) * 136 + dv];
                t1.x = Vs[(kv0 + 8) * 136 + dv];
                t1.y = Vs[(kv0 + 9) * 136 + dv];
                uint32_t vb[2] = { *(uint32_t*)&t0, *(uint32_t*)&t1 };
                mma_f16(o[vf], pa, vb);
            }
        }
    }

    // ======== fused linear-memory epilogue ========
    asm volatile("cp.async.wait_group 0;" ::: "memory");
    __syncthreads();                       // all warps done with Ks/Vs

    __half* sigq = smA + 17408;            // recycle Ks double-buffer
    __half* Mh   = smA + 34816;            // recycle Vs double-buffer
    float* zsm = (float*)(smA + 52224);    // 128 floats

    // sig_q = elu(Qs)+1 (half), M tile fp32 -> half
    {
        const float* Mg = Mpre + ((size_t)bh * 8 + seg) * 16384;
#pragma unroll
        for (int u = 0; u < 8; ++u) {
            int idx = tid + u * 256;
            int r = idx >> 4, c8 = (idx & 15) << 3;
            uint4 q4 = *(const uint4*)&Qs[r * 136 + c8];
            const __half* qh = (const __half*)&q4;
            __half2 qo[4];
#pragma unroll
            for (int i = 0; i < 4; ++i)
                qo[i] = __floats2half2_rn(elu1(__half2float(qh[2 * i])),
                                          elu1(__half2float(qh[2 * i + 1])));
            *(uint4*)&sigq[r * 136 + c8] = *(uint4*)qo;

            float4 mv0 = *(const float4*)&Mg[r * 128 + c8];
            float4 mv1 = *(const float4*)&Mg[r * 128 + c8 + 4];
            __half2 mo[4] = {
                __floats2half2_rn(mv0.x, mv0.y), __floats2half2_rn(mv0.z, mv0.w),
                __floats2half2_rn(mv1.x, mv1.y), __floats2half2_rn(mv1.z, mv1.w)
            };
            *(uint4*)&Mh[r * 136 + c8] = *(uint4*)mo;
        }
        if (tid < 128) zsm[tid] = zpre[((size_t)bh * 8 + seg) * 128 + tid];
    }
    __syncthreads();

    // stage normalized softmax output to Qs region (frees o[] registers; stride 136)
    const int r0 = w * 16 + group;
    {
        const float inv0 = 1.f / l0, inv1 = 1.f / l1;
#pragma unroll
        for (int vf = 0; vf < 16; ++vf) {
            const int dv = vf * 8 + tig * 2;
            *(__half2*)&Qs[r0 * 136 + dv] =
                __floats2half2_rn(o[vf][0] * inv0, o[vf][1] * inv0);
            *(__half2*)&Qs[(r0 + 8) * 136 + dv] =
                __floats2half2_rn(o[vf][2] * inv1, o[vf][3] * inv1);
        }
    }

    // om = sig_q @ M  (gemm A-pattern + pmat B-pattern)
    float om[16][4];
#pragma unroll
    for (int i = 0; i < 16; ++i)
#pragma unroll
        for (int j2 = 0; j2 < 4; ++j2) om[i][j2] = 0.f;

    const int a_base = (w * 16 + (lane & 15)) * 136 + ((lane >> 4) << 3);
    const int brow2 = (((lane >> 3) & 1) << 3) + (lane & 7);
    const int bcolo2 = (lane >> 4) << 3;

#pragma unroll
    for (int ks = 0; ks < 8; ++ks) {
        uint32_t af[4];
        ldsm4(af[0], af[1], af[2], af[3], smem_u32(sigq + a_base + ks * 16));
#pragma unroll
        for (int nf2 = 0; nf2 < 8; ++nf2) {
            uint32_t bf0[2], bf1[2];
            ldsm4t(bf0[0], bf0[1], bf1[0], bf1[1],
                   smem_u32(&Mh[(ks * 16 + brow2) * 136 + nf2 * 16 + bcolo2]));
            mma_f16(om[2 * nf2], af, bf0);
            mma_f16(om[2 * nf2 + 1], af, bf1);
        }
    }

    // denominator: sig_q . z (fp32, tig-split + shfl)
    float den0 = 0.f, den1 = 0.f;
#pragma unroll 8
    for (int d = tig * 32; d < tig * 32 + 32; ++d) {
        float zd = zsm[d];
        den0 += __half2float(sigq[r0 * 136 + d]) * zd;
        den1 += __half2float(sigq[(r0 + 8) * 136 + d]) * zd;
    }
    den0 += __shfl_xor_sync(0xffffffffu, den0, 1);
    den0 += __shfl_xor_sync(0xffffffffu, den0, 2);
    den1 += __shfl_xor_sync(0xffffffffu, den1, 1);
    den1 += __shfl_xor_sync(0xffffffffu, den1, 2);
    const float invd0 = 1.f / den0, invd1 = 1.f / den1;

    // gated blend (staged softmax from smem) + store
    const int grow0 = rowbase + qt * 128 + r0;
#pragma unroll
    for (int vf = 0; vf < 16; ++vf) {
        const int dv = vf * 8 + tig * 2;
        float g0 = 1.f / (1.f + __expf(-betas[h * 128 + dv]));
        float g1 = 1.f / (1.f + __expf(-betas[h * 128 + dv + 1]));
        __half2 so0 = *(const __half2*)&Qs[r0 * 136 + dv];
        __half2 so1 = *(const __half2*)&Qs[(r0 + 8) * 136 + dv];
        const size_t base0 = (size_t)grow0 * 2048 + h * 128 + dv;
        const size_t base1 = (size_t)(grow0 + 8) * 2048 + h * 128 + dv;
        *(__half2*)&att[base0] = __floats2half2_rn(
            g0 * (om[vf][0] * invd0) + (1.f - g0) * __half2float(so0.x),
            g1 * (om[vf][1] * invd0) + (1.f - g1) * __half2float(so0.y));
        *(__half2*)&att[base1] = __floats2half2_rn(
            g0 * (om[vf][2] * invd1) + (1.f - g0) * __half2float(so1.x),
            g1 * (om[vf][3] * invd1) + (1.f - g1) * __half2float(so1.y));
    }
}

// ---------------- per-segment memory outer product: tensor cores + fused z sums ----------------
__global__ __launch_bounds__(256, 2) void pmat_k(
    const __half* __restrict__ Kg, const __half* __restrict__ Vg,
    float* __restrict__ P, float* __restrict__ z)
{
    __shared__ __half skh[32 * 136];
    __shared__ __half svh[32 * 136];
    const int tid = threadIdx.x;
    const int wid = tid >> 5, lane = tid & 31;
    const int group = lane >> 2, tig = lane & 3;
    const int wm = wid >> 2, wn = wid & 3;
    const int seg = blockIdx.x, bh = blockIdx.y;
    const int b = bh >> 4, h = bh & 15;
    const int rowbase = b * 4096 + seg * 512;

    float acc[4][4][4] = {};
    float zacc = 0.f;

    const int arow = ((lane >> 4) << 3) + (lane & 7);
    const int acolo = ((lane >> 3) & 1) << 3;
    const int brow = (((lane >> 3) & 1) << 3) + (lane & 7);
    const int bcolo = (lane >> 4) << 3;

    for (int ck = 0; ck < 512; ck += 32) {
        __syncthreads();
#pragma unroll
        for (int u = 0; u < 2; ++u) {
            const int idx = tid + u * 256;
            const int r = idx >> 4;
            const int c8 = (idx & 15) << 3;
            const size_t gi = (size_t)(rowbase + ck + r) * 6144 + h * 128 + c8;
            uint4 k4 = *(const uint4*)&Kg[gi];
            const __half* kh = (const __half*)&k4;
            __half2 ko[4];
#pragma unroll
            for (int i = 0; i < 4; ++i)
                ko[i] = __floats2half2_rn(elu1(__half2float(kh[2 * i])),
                                          elu1(__half2float(kh[2 * i + 1])));
            *(uint4*)&skh[r * 136 + c8] = *(uint4*)ko;
            *(uint4*)&svh[r * 136 + c8] = *(const uint4*)&Vg[gi];
        }
        __syncthreads();

        if (tid < 128) {
#pragma unroll
            for (int s = 0; s < 32; ++s) zacc += __half2float(skh[s * 136 + tid]);
        }

#pragma unroll
        for (int kstep = 0; kstep < 2; ++kstep) {
            const int k0 = kstep * 16;
            uint32_t af[4][4], bf[4][2];
#pragma unroll
            for (int mf = 0; mf < 4; ++mf)
                ldsm4t(af[mf][0], af[mf][1], af[mf][2], af[mf][3],
                       smem_u32(&skh[(k0 + arow) * 136 + wm * 64 + mf * 16 + acolo]));
#pragma unroll
            for (int np = 0; np < 2; ++np)
                ldsm4t(bf[2 * np][0], bf[2 * np][1], bf[2 * np + 1][0], bf[2 * np + 1][1],
                       smem_u32(&svh[(k0 + brow) * 136 + wn * 32 + np * 16 + bcolo]));
#pragma unroll
            for (int mf = 0; mf < 4; ++mf)
#pragma unroll
                for (int nf = 0; nf < 4; ++nf)
                    mma_f16(acc[mf][nf], af[mf], bf[nf]);
        }
    }

    float* Pp = P + ((size_t)bh * 8 + seg) * 16384;
#pragma unroll
    for (int mf = 0; mf < 4; ++mf) {
        const int row = wm * 64 + mf * 16 + group;
#pragma unroll
        for (int nf = 0; nf < 4; ++nf) {
            const int col = wn * 32 + nf * 8 + 2 * tig;
            *(float2*)&Pp[row * 128 + col] = make_float2(acc[mf][nf][0], acc[mf][nf][1]);
            *(float2*)&Pp[(row + 8) * 128 + col] = make_float2(acc[mf][nf][2], acc[mf][nf][3]);
        }
    }
    if (tid < 128)
        z[((size_t)bh * 8 + seg) * 128 + tid] = zacc;
}

// ---------------- exclusive prefix over segments (grid 32x8) ----------------
__global__ void prefix_k(const float* __restrict__ P, const float* __restrict__ z,
                         float* __restrict__ Mpre, float* __restrict__ zpre)
{
    const int bh = blockIdx.x;
    const int part = blockIdx.y;
    const int tid = threadIdx.x;
    const int i0 = part * 2048;
    for (int idx = i0 + tid; idx < i0 + 2048; idx += 256) {
        float run = 0.f;
        for (int s = 0; s < 8; ++s) {
            size_t o = ((size_t)bh * 8 + s) * 16384 + idx;
            Mpre[o] = run;
            run += P[o];
        }
    }
    if (part == 0 && tid < 128) {
        float run = 1.f / 128.f;
        for (int s = 0; s < 8; ++s) {
            size_t o = ((size_t)bh * 8 + s) * 128 + tid;
            zpre[o] = run;
            run += z[o];
        }
    }
}

// ---------------- residual + LayerNorm (vectorized, smem row cache) ----------------
__global__ __launch_bounds__(256) void ln_k(
    const float* __restrict__ y, const float* __restrict__ x,
    const float* __restrict__ gm, const float* __restrict__ bt,
    float* __restrict__ out)
{
    __shared__ float buf[2048];
    __shared__ float r1[8], r2[8];
    const int row = blockIdx.x, tid = threadIdx.x;
    const float* yp = y + (size_t)row * 2048;
    const float* xp = x + (size_t)row * 2048;
    float s1 = 0.f, s2 = 0.f;
#pragma unroll
    for (int u = 0; u < 2; ++u) {
        const int c = (tid + u * 256) * 4;
        float4 yv = *(const float4*)&yp[c];
        float4 xv = *(const float4*)&xp[c];
        float4 v = make_float4(yv.x + xv.x, yv.y + xv.y, yv.z + xv.z, yv.w + xv.w);
        *(float4*)&buf[c] = v;
        s1 += v.x + v.y + v.z + v.w;
        s2 += v.x * v.x + v.y * v.y + v.z * v.z + v.w * v.w;
    }
#pragma unroll
    for (int off = 16; off >= 1; off >>= 1) {
        s1 += __shfl_xor_sync(0xffffffffu, s1, off);
        s2 += __shfl_xor_sync(0xffffffffu, s2, off);
    }
    if ((tid & 31) == 0) { r1[tid >> 5] = s1; r2[tid >> 5] = s2; }
    __syncthreads();
    if (tid == 0) {
        float a = 0.f, bb = 0.f;
        for (int w = 0; w < 8; ++w) { a += r1[w]; bb += r2[w]; }
        r1[0] = a; r2[0] = bb;
    }
    __syncthreads();
    const float mu = r1[0] * (1.f / 2048.f);
    const float var = r2[0] * (1.f / 2048.f) - mu * mu;
    const float rs = rsqrtf(var + 1e-5f);
#pragma unroll
    for (int u = 0; u < 2; ++u) {
        const int c = (tid + u * 256) * 4;
        float4 v = *(const float4*)&buf[c];
        float4 g = *(const float4*)&gm[c];
        float4 bb = *(const float4*)&bt[c];
        float4 oo;
        oo.x = (v.x - mu) * rs * g.x + bb.x;
        oo.y = (v.y - mu) * rs * g.y + bb.y;
        oo.z = (v.z - mu) * rs * g.z + bb.z;
        oo.w = (v.w - mu) * rs * g.w + bb.w;
        *(float4*)&out[(size_t)row * 2048 + c] = oo;
    }
}

// ---------------- host ----------------
extern "C" void kernel_launch(void* const* d_in, const int* in_sizes, int n_in,
                              void* d_out, int out_size)
{
    const float* x     = (const float*)d_in[0];
    const float* Wq    = (const float*)d_in[1];
    const float* Wk    = (const float*)d_in[2];
    const float* Wv    = (const float*)d_in[3];
    const float* Wo    = (const float*)d_in[4];
    const float* betas = (const float*)d_in[5];
    const float* W1    = (const float*)d_in[6];
    const float* b1    = (const float*)d_in[7];
    const float* W2    = (const float*)d_in[8];
    const float* b2    = (const float*)d_in[9];
    const float* lng   = (const float*)d_in[10];
    const float* lnb   = (const float*)d_in[11];
    float* out = (float*)d_out;

    float *Pb, *Mp, *zb, *zp, *YB;
    __half *QKV, *XH, *AT, *AO, *HB, *WqkvT, *WoT, *W1T, *W2T;
    cudaGetSymbolAddress((void**)&QKV, g_qkv);
    cudaGetSymbolAddress((void**)&XH, g_xh);
    cudaGetSymbolAddress((void**)&AT, g_att);
    cudaGetSymbolAddress((void**)&Pb, g_P);
    cudaGetSymbolAddress((void**)&Mp, g_Mpre);
    cudaGetSymbolAddress((void**)&zb, g_zz);
    cudaGetSymbolAddress((void**)&zp, g_zpre);
    cudaGetSymbolAddress((void**)&AO, g_ao);
    cudaGetSymbolAddress((void**)&HB, g_hb);
    cudaGetSymbolAddress((void**)&YB, g_yb);
    cudaGetSymbolAddress((void**)&WqkvT, g_WqkvT);
    cudaGetSymbolAddress((void**)&WoT, g_WoT);
    cudaGetSymbolAddress((void**)&W1T, g_W1T);
    cudaGetSymbolAddress((void**)&W2T, g_W2T);

    const __half* Kb = QKV + 2048;

    cudaFuncSetAttribute(attn_fused, cudaFuncAttributeMaxDynamicSharedMemorySize, ATT2_SMEM);
    cudaFuncSetAttribute((const void*)gemm_mma<false, false, __half>, cudaFuncAttributeMaxDynamicSharedMemorySize, GEMM_SMEM);
    cudaFuncSetAttribute((const void*)gemm_mma<true, true, __half>,   cudaFuncAttributeMaxDynamicSharedMemorySize, GEMM_SMEM);
    cudaFuncSetAttribute((const void*)gemm_mma<true, false, float>,   cudaFuncAttributeMaxDynamicSharedMemorySize, GEMM_SMEM);

    // ---- input convert + weight transposes ----
    cvt_h<<<8192, 256>>>(x, XH);
    transpose4_h<<<dim3(64, 64, 4), 256>>>(Wq, Wk, Wv, Wo, WqkvT, WoT);
    transpose_h<<<dim3(256, 64), 256>>>(W1, W1T, 2048, 8192);
    transpose_h<<<dim3(64, 256), 256>>>(W2, W2T, 8192, 2048);

    // ---- fused QKV projection (half out) ----
    gemm_mma<false, false, __half><<<dim3(48, 64), 256, GEMM_SMEM>>>(XH, WqkvT, nullptr, QKV, 6144, 2048);

    // ---- linear memory path first (attn_fused consumes Mpre/zpre) ----
    dim3 gz(8, 32);
    pmat_k<<<gz, 256>>>(Kb, QKV + 4096, Pb, zb);
    prefix_k<<<dim3(32, 8), 256>>>(Pb, zb, Mp, zp);

    // ---- fused attention (softmax + memory + blend) ----
    attn_fused<<<dim3(4, 8, 32), 256, ATT2_SMEM>>>(QKV, Mp, zp, betas, AT);

    // ---- output projection + MLP ----
    gemm_mma<false, false, __half><<<dim3(16, 64), 256, GEMM_SMEM>>>(AT, WoT, nullptr, AO, 2048, 2048);
    gemm_mma<true, true, __half><<<dim3(64, 64), 256, GEMM_SMEM>>>(AO, W1T, b1, HB, 8192, 2048);
    gemm_mma<true, false, float><<<dim3(16, 64), 256, GEMM_SMEM>>>(HB, W2T, b2, YB, 2048, 8192);

    // ---- residual + LayerNorm ----
    ln_k<<<8192, 256>>>(YB, x, lng, lnb, out);
}